// round 5
// baseline (speedup 1.0000x reference)
#include <cuda_runtime.h>

#define NROWS 256
#define NBLK  1024
#define P1_SLICES (NBLK / NROWS)   // 4

// Scratch (no cudaMalloc). __device__ globals zero-init at module load.
__device__ float d_partial[NROWS * P1_SLICES];
__device__ float d_row_mean[NROWS];
__device__ unsigned int d_count[NROWS];
__device__ unsigned int g_arrive;
__device__ unsigned int g_gen;

__device__ __forceinline__ void grid_barrier() {
    __syncthreads();
    if (threadIdx.x == 0) {
        __threadfence();
        unsigned int gen = *((volatile unsigned int*)&g_gen);
        unsigned int my = atomicAdd(&g_arrive, 1u);
        if (my == (unsigned int)(gridDim.x - 1)) {
            g_arrive = 0;
            __threadfence();
            atomicAdd(&g_gen, 1u);   // release
        } else {
            while (*((volatile unsigned int*)&g_gen) == gen) { }
        }
    }
    __syncthreads();
}

__global__ __launch_bounds__(256, 8) void fused_kernel(const float* __restrict__ c1,
                                                       const float* __restrict__ c2,
                                                       float* __restrict__ out,
                                                       int row_elems) {
    const int tid   = threadIdx.x;
    const int row   = blockIdx.x & (NROWS - 1);
    const int slice = blockIdx.x >> 8;           // 0..3
    const int n4        = row_elems >> 2;        // 12544
    const int per_slice = n4 / P1_SLICES;        // 3136
    const size_t row_base = (size_t)row * row_elems;

    // ---------- Phase 1: partial reduce of conv1[row], slice ----------
    {
        const float4* p = reinterpret_cast<const float4*>(c1 + row_base) + slice * per_slice;
        float s0 = 0.f, s1 = 0.f, s2 = 0.f, s3 = 0.f;
        int i = tid;
        for (; i + 768 < per_slice; i += 1024) {   // 4 front-batched loads -> MLP 4
            float4 a0 = p[i];
            float4 a1 = p[i + 256];
            float4 a2 = p[i + 512];
            float4 a3 = p[i + 768];
            s0 += (a0.x + a0.y) + (a0.z + a0.w);
            s1 += (a1.x + a1.y) + (a1.z + a1.w);
            s2 += (a2.x + a2.y) + (a2.z + a2.w);
            s3 += (a3.x + a3.y) + (a3.z + a3.w);
        }
        for (; i < per_slice; i += 256) {
            float4 a = p[i];
            s0 += (a.x + a.y) + (a.z + a.w);
        }
        float s = (s0 + s1) + (s2 + s3);

        #pragma unroll
        for (int o = 16; o > 0; o >>= 1)
            s += __shfl_xor_sync(0xffffffffu, s, o);

        __shared__ float warp_sums[8];
        const int lane = tid & 31;
        const int wid  = tid >> 5;
        if (lane == 0) warp_sums[wid] = s;
        __syncthreads();

        if (tid == 0) {
            float t = 0.f;
            #pragma unroll
            for (int w = 0; w < 8; w++) t += warp_sums[w];
            d_partial[row * P1_SLICES + slice] = t;
            __threadfence();
            unsigned int old = atomicAdd(&d_count[row], 1u);
            if (old == P1_SLICES - 1) {
                // Last slice-block for this row: fixed-order sum -> deterministic.
                const volatile float* vp = d_partial;
                float sum = 0.f;
                #pragma unroll
                for (int k = 0; k < P1_SLICES; k++)
                    sum += vp[row * P1_SLICES + k];
                d_row_mean[row] = sum / (float)row_elems;
                d_count[row] = 0;  // self-reset for next graph replay
            }
        }
    }

    // ---------- Grid-wide barrier: all means published ----------
    grid_barrier();

    // ---------- Phase 2: out[row, slice-range] = mean * conv2 ----------
    {
        const float m = *((volatile float*)&d_row_mean[row]);
        const float4* src = reinterpret_cast<const float4*>(c2 + row_base) + slice * per_slice;
        float4* dst = reinterpret_cast<float4*>(out + row_base) + slice * per_slice;
        int i = tid;
        for (; i + 768 < per_slice; i += 1024) {
            float4 a0 = src[i];
            float4 a1 = src[i + 256];
            float4 a2 = src[i + 512];
            float4 a3 = src[i + 768];
            a0.x *= m; a0.y *= m; a0.z *= m; a0.w *= m;
            a1.x *= m; a1.y *= m; a1.z *= m; a1.w *= m;
            a2.x *= m; a2.y *= m; a2.z *= m; a2.w *= m;
            a3.x *= m; a3.y *= m; a3.z *= m; a3.w *= m;
            dst[i]       = a0;
            dst[i + 256] = a1;
            dst[i + 512] = a2;
            dst[i + 768] = a3;
        }
        for (; i < per_slice; i += 256) {
            float4 a = src[i];
            a.x *= m; a.y *= m; a.z *= m; a.w *= m;
            dst[i] = a;
        }
    }
}

extern "C" void kernel_launch(void* const* d_in, const int* in_sizes, int n_in,
                              void* d_out, int out_size) {
    const float* c1 = (const float*)d_in[0];
    const float* c2 = (const float*)d_in[1];
    float* out = (float*)d_out;

    const int row_elems = in_sizes[0] / NROWS;  // 50176

    fused_kernel<<<NBLK, 256>>>(c1, c2, out, row_elems);
}

// round 6
// speedup vs baseline: 1.0094x; 1.0094x over previous
#include <cuda_runtime.h>

#define NROWS 256
#define CHUNKS 49   // 12544 float4 per row / 256 per block

// Scratch (no cudaMalloc). __device__ globals zero-init at module load.
__device__ float d_partial[NROWS * CHUNKS];
__device__ float d_row_mean[NROWS];
__device__ unsigned int d_count[NROWS];

// Kernel 1: grid (49, 256), block 256. Each thread loads ONE float4 of
// conv1[row] (same launch shape as the known-6.7TB/s scale kernel), block
// reduces, writes a partial. Last block per row sums 49 partials in fixed
// order (deterministic), publishes the mean, resets the counter.
__global__ __launch_bounds__(256) void row_mean_kernel(const float* __restrict__ c1,
                                                       int row_elems) {
    const int row = blockIdx.y;
    const int tid = threadIdx.x;
    const float4* p = reinterpret_cast<const float4*>(c1 + (size_t)row * row_elems);

    float4 v = p[blockIdx.x * 256 + tid];
    float s = (v.x + v.y) + (v.z + v.w);

    #pragma unroll
    for (int o = 16; o > 0; o >>= 1)
        s += __shfl_xor_sync(0xffffffffu, s, o);

    __shared__ float warp_sums[8];
    const int lane = tid & 31;
    const int wid  = tid >> 5;
    if (lane == 0) warp_sums[wid] = s;
    __syncthreads();

    if (tid == 0) {
        float t = 0.f;
        #pragma unroll
        for (int w = 0; w < 8; w++) t += warp_sums[w];

        d_partial[row * CHUNKS + blockIdx.x] = t;
        __threadfence();
        unsigned int old = atomicAdd(&d_count[row], 1u);
        if (old == CHUNKS - 1) {
            // Last block for this row: fixed-order sum -> deterministic.
            const volatile float* vp = d_partial + row * CHUNKS;
            float sum = 0.f;
            #pragma unroll
            for (int k = 0; k < CHUNKS; k++)
                sum += vp[k];
            d_row_mean[row] = sum / (float)row_elems;
            d_count[row] = 0;  // self-reset for next graph replay
        }
    }
}

// Kernel 2: out[row, :] = mean[row] * c2[row, :]. Known-good 6.7 TB/s body:
// single broadcast mean load, then pure float4 stream.
__global__ __launch_bounds__(256) void scale_kernel(const float* __restrict__ c2,
                                                    float* __restrict__ out,
                                                    int row_elems) {
    const int row = blockIdx.y;
    const float m = d_row_mean[row];
    const size_t base = (size_t)row * row_elems;
    const float4* src = reinterpret_cast<const float4*>(c2 + base);
    float4* dst = reinterpret_cast<float4*>(out + base);
    const int i = blockIdx.x * blockDim.x + threadIdx.x;
    float4 v = src[i];
    v.x *= m; v.y *= m; v.z *= m; v.w *= m;
    dst[i] = v;
}

extern "C" void kernel_launch(void* const* d_in, const int* in_sizes, int n_in,
                              void* d_out, int out_size) {
    const float* c1 = (const float*)d_in[0];
    const float* c2 = (const float*)d_in[1];
    float* out = (float*)d_out;

    const int row_elems = in_sizes[0] / NROWS;  // 50176

    dim3 grid(CHUNKS, NROWS);                   // 49 x 256 = 12544 blocks
    row_mean_kernel<<<grid, 256>>>(c1, row_elems);
    scale_kernel<<<grid, 256>>>(c2, out, row_elems);
}

// round 7
// speedup vs baseline: 1.1347x; 1.1242x over previous
#include <cuda_runtime.h>

#define NROWS 256
#define NSLICE 8

// Scratch (no cudaMalloc). __device__ globals zero-init at module load.
__device__ float d_partial[NROWS * NSLICE];
__device__ float d_row_mean[NROWS];
__device__ unsigned int d_count[NROWS];

// Kernel 1: EXACT R3 reduce body (measured 12.5us) + R4's folded finalize.
// grid (NSLICE, 256). Block (s, row) reduces slice s of row `row`.
// 50176 floats -> 12544 float4 -> 1568 float4/slice, 256 threads, dual-acc.
__global__ __launch_bounds__(256) void row_partial_kernel(const float* __restrict__ c1,
                                                          int row_elems) {
    const int row = blockIdx.y;
    const int slice = blockIdx.x;
    const int n4 = row_elems >> 2;          // 12544
    const int per_slice = n4 / NSLICE;      // 1568
    const float4* p = reinterpret_cast<const float4*>(c1 + (size_t)row * row_elems)
                      + slice * per_slice;

    float s0 = 0.f, s1 = 0.f;
    int i = threadIdx.x;
    for (; i + 256 < per_slice; i += 512) {
        float4 a = p[i];
        float4 b = p[i + 256];
        s0 += (a.x + a.y) + (a.z + a.w);
        s1 += (b.x + b.y) + (b.z + b.w);
    }
    if (i < per_slice) {
        float4 a = p[i];
        s0 += (a.x + a.y) + (a.z + a.w);
    }
    float s = s0 + s1;

    #pragma unroll
    for (int o = 16; o > 0; o >>= 1)
        s += __shfl_xor_sync(0xffffffffu, s, o);

    __shared__ float warp_sums[8];
    const int lane = threadIdx.x & 31;
    const int wid = threadIdx.x >> 5;
    if (lane == 0) warp_sums[wid] = s;
    __syncthreads();

    if (threadIdx.x == 0) {
        float t = 0.f;
        #pragma unroll
        for (int w = 0; w < 8; w++) t += warp_sums[w];

        d_partial[row * NSLICE + slice] = t;
        __threadfence();
        unsigned int old = atomicAdd(&d_count[row], 1u);
        if (old == NSLICE - 1) {
            // Last block for this row: fixed-order sum -> deterministic.
            const volatile float* vp = d_partial + row * NSLICE;
            float sum = 0.f;
            #pragma unroll
            for (int k = 0; k < NSLICE; k++)
                sum += vp[k];
            d_row_mean[row] = sum / (float)row_elems;
            d_count[row] = 0;  // self-reset for next graph replay
        }
    }
}

// Kernel 2: EXACT R1 scale body (measured 15.0-15.4us, 6.7 TB/s aggregate).
__global__ __launch_bounds__(256) void scale_kernel(const float* __restrict__ c2,
                                                    float* __restrict__ out,
                                                    int row_elems) {
    const int row = blockIdx.y;
    const float m = d_row_mean[row];
    const size_t base = (size_t)row * row_elems;
    const float4* src = reinterpret_cast<const float4*>(c2 + base);
    float4* dst = reinterpret_cast<float4*>(out + base);
    const int i = blockIdx.x * blockDim.x + threadIdx.x;
    float4 v = src[i];
    v.x *= m; v.y *= m; v.z *= m; v.w *= m;
    dst[i] = v;
}

extern "C" void kernel_launch(void* const* d_in, const int* in_sizes, int n_in,
                              void* d_out, int out_size) {
    const float* c1 = (const float*)d_in[0];
    const float* c2 = (const float*)d_in[1];
    float* out = (float*)d_out;

    const int row_elems = in_sizes[0] / NROWS;  // 50176

    dim3 rgrid(NSLICE, NROWS);                  // 8 x 256 = 2048 blocks
    row_partial_kernel<<<rgrid, 256>>>(c1, row_elems);

    const int n4_per_row = row_elems >> 2;      // 12544
    dim3 sgrid(n4_per_row / 256, NROWS);        // 49 x 256
    scale_kernel<<<sgrid, 256>>>(c2, out, row_elems);
}